// round 8
// baseline (speedup 1.0000x reference)
#include <cuda_runtime.h>
#include <cuda_fp16.h>

// Problem constants (fixed by the dataset)
#define NN 100000
#define CC 48
#define EE 1600000
#define MM 20000
#define LL 10
#define LAMF 0.9f
#define OMLAMF 0.1f

#define XSTRIDE 64   // halves per x-row (128B padded) -> gathers hit one cache line

#define SCAN_BLOCK 1024
#define SCAN_ITEMS 4
#define SCAN_TILE  (SCAN_BLOCK * SCAN_ITEMS)            // 4096
#define NTILES     ((NN + SCAN_TILE - 1) / SCAN_TILE)   // 25

// padded edge capacity: each row padded to even count -> <= EE + NN int2 entries
#define PADE  (EE + NN)
#define PADE4 ((PADE + 1) / 2)

// ---------------- device scratch (no allocations allowed) ----------------
__device__ int    d_deg[NN];
__device__ float  d_dinv[NN];
__device__ int    d_rowcnt[NN];       // true out-count per row
__device__ int    d_rowptr[NN];       // CSR offsets in PADDED (even) int2 space
__device__ int    d_cursor[NN];
__device__ int    d_winner[NN];       // last mask index targeting node (-1)
__device__ int4   d_edges4[PADE4];    // {col0,w0,col1,w1}; w prescaled by LAM; pads w=0
__device__ float  d_G01f[NN * CC];    // 0.1*G fp32 (final iter)
__device__ __half d_G01h[NN * CC];    // 0.1*G fp16 (intermediate iters)
__device__ __half d_xA[NN * XSTRIDE]; // fp16 ping (128B row stride)
__device__ __half d_xB[NN * XSTRIDE]; // fp16 pong (holds x0)
__device__ int    d_tileSum[NTILES];

__device__ __forceinline__ int padded(int c) { return (c + 1) & ~1; }

// ---------------- preprocessing (5 kernels, unchanged from 469us baseline) ----
__global__ void k_init() {
    int i = blockIdx.x * blockDim.x + threadIdx.x;
    if (i < NN) {
        d_deg[i] = 0;
        d_rowcnt[i] = 0;
        d_winner[i] = -1;
    }
}

__global__ void k_count(const int* __restrict__ row, const int* __restrict__ col,
                        const int* __restrict__ mask) {
    int e = blockIdx.x * blockDim.x + threadIdx.x;
    if (e < EE) {
        atomicAdd(&d_rowcnt[row[e]], 1);
        atomicAdd(&d_deg[col[e]], 1);
    }
    if (e < MM) atomicMax(&d_winner[mask[e]], e);
}

__global__ void k_scan_reduce() {
    __shared__ int sdata[SCAN_BLOCK];
    int t = threadIdx.x, b = blockIdx.x;
    int base = b * SCAN_TILE;
    int s = 0;
#pragma unroll
    for (int i = 0; i < SCAN_ITEMS; i++) {
        int idx = base + t + i * SCAN_BLOCK;
        if (idx < NN) {
            s += padded(d_rowcnt[idx]);
            d_dinv[idx] = rsqrtf((float)d_deg[idx]);   // deg >= 1 guaranteed
        }
    }
    sdata[t] = s;
    __syncthreads();
    for (int o = SCAN_BLOCK / 2; o > 0; o >>= 1) {
        if (t < o) sdata[t] += sdata[t + o];
        __syncthreads();
    }
    if (t == 0) d_tileSum[b] = sdata[0];
}

__global__ void k_scan_final() {
    __shared__ int ssum[SCAN_BLOCK];
    int t = threadIdx.x, b = blockIdx.x;
    int base = b * SCAN_TILE;
    int tileOff = 0;
    for (int i = 0; i < b; i++) tileOff += d_tileSum[i];

    int tc[SCAN_ITEMS], v[SCAN_ITEMS];
    int s = 0;
#pragma unroll
    for (int i = 0; i < SCAN_ITEMS; i++) {
        int idx = base + t * SCAN_ITEMS + i;
        tc[i] = (idx < NN) ? d_rowcnt[idx] : 0;
        v[i] = (idx < NN) ? padded(tc[i]) : 0;
        s += v[i];
    }
    ssum[t] = s;
    __syncthreads();
    for (int o = 1; o < SCAN_BLOCK; o <<= 1) {
        int val = ssum[t];
        int add = (t >= o) ? ssum[t - o] : 0;
        __syncthreads();
        ssum[t] = val + add;
        __syncthreads();
    }
    int run = ((t > 0) ? ssum[t - 1] : 0) + tileOff;
#pragma unroll
    for (int i = 0; i < SCAN_ITEMS; i++) {
        int idx = base + t * SCAN_ITEMS + i;
        if (idx < NN) {
            d_rowptr[idx] = run;
            d_cursor[idx] = run;
            if (tc[i] & 1)
                ((int2*)d_edges4)[run + tc[i]] = make_int2(0, 0);
            run += v[i];
        }
    }
}

__global__ void k_fill_buildG(const int* __restrict__ row, const int* __restrict__ col,
                              const float* __restrict__ Z, const float* __restrict__ Y) {
    int idx = blockIdx.x * blockDim.x + threadIdx.x;
    if (idx < EE) {
        int r = row[idx], c = col[idx];
        float w = LAMF * d_dinv[r] * d_dinv[c];
        int pos = atomicAdd(&d_cursor[r], 1);
        ((int2*)d_edges4)[pos] = make_int2(c, __float_as_int(w));
    }
    if (idx < NN * CC) {
        int n = idx / CC, c = idx % CC;
        int wi = d_winner[n];
        float g = (wi >= 0) ? Y[wi * CC + c] : Z[idx];
        float g01 = OMLAMF * g;
        d_G01f[idx] = g01;
        d_G01h[idx] = __float2half_rn(g01);
        d_xB[(size_t)n * XSTRIDE + c] = __float2half_rn(g);   // x0, padded stride
    }
}

// ---------------- SpMM: warp-per-row, QUARTER-WARP uint4 gather --------------
// 4 edges per trip: quarter q (8 lanes, 6 active) handles edge 4t+q.
// Active lane gathers uint4 = 16B = 8 halves of the edge's x-row.
// Edge pairs prefetched one trip ahead. Pad entries have w==0 -> gather skipped.
// End: shfl_xor(8) + shfl_xor(16) merge quarters; quarter 0 writes.
__device__ __forceinline__ void qproc(unsigned c, float w, bool on,
                                      const char* __restrict__ xb, unsigned bofs,
                                      float* acc) {
    if (on) {
        uint4 raw = __ldg((const uint4*)(xb + (c << 7) + bofs));
        __half2 h0, h1, h2, h3;
        *reinterpret_cast<unsigned*>(&h0) = raw.x;
        *reinterpret_cast<unsigned*>(&h1) = raw.y;
        *reinterpret_cast<unsigned*>(&h2) = raw.z;
        *reinterpret_cast<unsigned*>(&h3) = raw.w;
        float2 f0 = __half22float2(h0);
        float2 f1 = __half22float2(h1);
        float2 f2 = __half22float2(h2);
        float2 f3 = __half22float2(h3);
        acc[0] = fmaf(w, f0.x, acc[0]);
        acc[1] = fmaf(w, f0.y, acc[1]);
        acc[2] = fmaf(w, f1.x, acc[2]);
        acc[3] = fmaf(w, f1.y, acc[3]);
        acc[4] = fmaf(w, f2.x, acc[4]);
        acc[5] = fmaf(w, f2.y, acc[5]);
        acc[6] = fmaf(w, f3.x, acc[6]);
        acc[7] = fmaf(w, f3.y, acc[7]);
    }
}

template <bool FINAL>
__global__ __launch_bounds__(256, 6) void k_spmm(const __half* __restrict__ x,
                                                 void* __restrict__ outp) {
    int gw = (blockIdx.x * blockDim.x + threadIdx.x) >> 5;
    if (gw >= NN) return;
    const int lane = threadIdx.x & 31;
    const int q = lane >> 3;          // quarter 0..3
    const int sub = lane & 7;
    const bool active = sub < 6;
    const unsigned bofs = sub * 16;   // byte offset of this lane's uint4 in a row

    const int np = (d_rowcnt[gw] + 1) >> 1;          // int4 pair count (>=1)
    const int4* ep = d_edges4 + (d_rowptr[gw] >> 1);
    const char* xb = (const char*)x;

    float acc[8];
#pragma unroll
    for (int k = 0; k < 8; k++) acc[k] = 0.f;

    const int ntrip = (np + 1) >> 1;                 // 2 pairs (4 edges) per trip
    int4 pA = __ldg(ep);
    int4 pB = (np > 1) ? __ldg(ep + 1) : make_int4(0, 0, 0, 0);

    for (int t = 0; t < ntrip; t++) {
        int4 nA = make_int4(0, 0, 0, 0), nB = make_int4(0, 0, 0, 0);
        int nxt = 2 * t + 2;
        if (nxt < np)     nA = __ldg(ep + nxt);
        if (nxt + 1 < np) nB = __ldg(ep + nxt + 1);

        int4 p = (q < 2) ? pA : pB;
        unsigned c = (unsigned)((q & 1) ? p.z : p.x);
        float w = __int_as_float((q & 1) ? p.w : p.y);
        qproc(c, w, active && (w != 0.f), xb, bofs, acc);

        pA = nA;
        pB = nB;
    }

    // merge quarters: q0+=q1, q2+=q3 (xor 8), then +q2 (xor 16)
#pragma unroll
    for (int k = 0; k < 8; k++) acc[k] += __shfl_xor_sync(0xffffffff, acc[k], 8);
#pragma unroll
    for (int k = 0; k < 8; k++) acc[k] += __shfl_xor_sync(0xffffffff, acc[k], 16);

    if (q == 0 && active) {
        unsigned go = (unsigned)gw * CC + sub * 8;   // this lane's 8 floats
        if (FINAL) {
            const float4 g0 = *(const float4*)(d_G01f + go);
            const float4 g1 = *(const float4*)(d_G01f + go + 4);
            float4 o0, o1;
            o0.x = acc[0] + g0.x;  o0.y = acc[1] + g0.y;
            o0.z = acc[2] + g0.z;  o0.w = acc[3] + g0.w;
            o1.x = acc[4] + g1.x;  o1.y = acc[5] + g1.y;
            o1.z = acc[6] + g1.z;  o1.w = acc[7] + g1.w;
            *(float4*)((float*)outp + go) = o0;
            *(float4*)((float*)outp + go + 4) = o1;
        } else {
            uint4 graw = *(const uint4*)(d_G01h + go);
            __half2 g0, g1, g2, g3;
            *reinterpret_cast<unsigned*>(&g0) = graw.x;
            *reinterpret_cast<unsigned*>(&g1) = graw.y;
            *reinterpret_cast<unsigned*>(&g2) = graw.z;
            *reinterpret_cast<unsigned*>(&g3) = graw.w;
            float2 gf0 = __half22float2(g0);
            float2 gf1 = __half22float2(g1);
            float2 gf2 = __half22float2(g2);
            float2 gf3 = __half22float2(g3);
            __half2 o0 = __floats2half2_rn(acc[0] + gf0.x, acc[1] + gf0.y);
            __half2 o1 = __floats2half2_rn(acc[2] + gf1.x, acc[3] + gf1.y);
            __half2 o2 = __floats2half2_rn(acc[4] + gf2.x, acc[5] + gf2.y);
            __half2 o3 = __floats2half2_rn(acc[6] + gf3.x, acc[7] + gf3.y);
            uint4 st;
            st.x = *reinterpret_cast<unsigned*>(&o0);
            st.y = *reinterpret_cast<unsigned*>(&o1);
            st.z = *reinterpret_cast<unsigned*>(&o2);
            st.w = *reinterpret_cast<unsigned*>(&o3);
            *(uint4*)((char*)outp + ((unsigned)gw << 7) + bofs) = st;
        }
    }
}

// ---------------- launch ----------------
extern "C" void kernel_launch(void* const* d_in, const int* in_sizes, int n_in,
                              void* d_out, int out_size) {
    const float* Z = (const float*)d_in[0];
    const float* Y = (const float*)d_in[1];
    const int* mask = (const int*)d_in[2];
    const int* ei = (const int*)d_in[3];   // [2, E]: row then col
    const int* row = ei;
    const int* col = ei + EE;

    __half *xA, *xB;
    cudaGetSymbolAddress((void**)&xA, d_xA);
    cudaGetSymbolAddress((void**)&xB, d_xB);

    const int tb = 256;
    k_init<<<(NN + tb - 1) / tb, tb>>>();
    k_count<<<(EE + tb - 1) / tb, tb>>>(row, col, mask);
    k_scan_reduce<<<NTILES, SCAN_BLOCK>>>();
    k_scan_final<<<NTILES, SCAN_BLOCK>>>();
    k_fill_buildG<<<(NN * CC + tb - 1) / tb, tb>>>(row, col, Z, Y);

    const int spmm_blocks = (NN * 32 + tb - 1) / tb;
    const __half* cur = xB;                  // x0
    for (int it = 0; it < LL - 1; ++it) {
        __half* nxt = (it & 1) ? xB : xA;
        k_spmm<false><<<spmm_blocks, tb>>>(cur, nxt);
        cur = nxt;
    }
    k_spmm<true><<<spmm_blocks, tb>>>(cur, d_out);
}

// round 9
// speedup vs baseline: 1.3871x; 1.3871x over previous
#include <cuda_runtime.h>
#include <cuda_fp16.h>

// Problem constants (fixed by the dataset)
#define NN 100000
#define CC 48
#define EE 1600000
#define MM 20000
#define LL 10
#define LAMF 0.9f
#define OMLAMF 0.1f

#define XSTRIDE 64   // halves per x-row (128B padded) -> gathers hit one cache line

#define SCAN_BLOCK 1024
#define SCAN_ITEMS 4
#define SCAN_TILE  (SCAN_BLOCK * SCAN_ITEMS)            // 4096
#define NTILES     ((NN + SCAN_TILE - 1) / SCAN_TILE)   // 25

// padded edge capacity: each row padded to even count; +2 slack for prefetch overread
#define PADE  (EE + NN + 2)

// ---------------- device scratch (no allocations allowed) ----------------
__device__ int    d_deg[NN];
__device__ float  d_dinv[NN];
__device__ int    d_rowcnt[NN];       // true out-count per row
__device__ int    d_rowptr[NN];       // CSR offsets in PADDED (even) int2 space
__device__ int    d_cursor[NN];
__device__ int    d_winner[NN];       // last mask index targeting node (-1)
__device__ int2   d_edges[PADE];      // {col, w}; w prescaled by LAM; pads w=0
__device__ float  d_G01f[NN * CC];    // 0.1*G fp32 (final iter)
__device__ __half d_G01h[NN * CC];    // 0.1*G fp16 (intermediate iters)
__device__ __half d_xA[NN * XSTRIDE]; // fp16 ping (128B row stride)
__device__ __half d_xB[NN * XSTRIDE]; // fp16 pong (holds x0)
__device__ int    d_tileSum[NTILES];

__device__ __forceinline__ int padded(int c) { return (c + 1) & ~1; }

// ---------------- preprocessing (5 kernels) ----------------
__global__ void k_init() {
    int i = blockIdx.x * blockDim.x + threadIdx.x;
    if (i < NN) {
        d_deg[i] = 0;
        d_rowcnt[i] = 0;
        d_winner[i] = -1;
    }
    if (i < 2) d_edges[EE + NN + i] = make_int2(0, 0);   // prefetch slack
}

__global__ void k_count(const int* __restrict__ row, const int* __restrict__ col,
                        const int* __restrict__ mask) {
    int e = blockIdx.x * blockDim.x + threadIdx.x;
    if (e < EE) {
        atomicAdd(&d_rowcnt[row[e]], 1);
        atomicAdd(&d_deg[col[e]], 1);
    }
    if (e < MM) atomicMax(&d_winner[mask[e]], e);
}

__global__ void k_scan_reduce() {
    __shared__ int sdata[SCAN_BLOCK];
    int t = threadIdx.x, b = blockIdx.x;
    int base = b * SCAN_TILE;
    int s = 0;
#pragma unroll
    for (int i = 0; i < SCAN_ITEMS; i++) {
        int idx = base + t + i * SCAN_BLOCK;
        if (idx < NN) {
            s += padded(d_rowcnt[idx]);
            d_dinv[idx] = rsqrtf((float)d_deg[idx]);   // deg >= 1 guaranteed
        }
    }
    sdata[t] = s;
    __syncthreads();
    for (int o = SCAN_BLOCK / 2; o > 0; o >>= 1) {
        if (t < o) sdata[t] += sdata[t + o];
        __syncthreads();
    }
    if (t == 0) d_tileSum[b] = sdata[0];
}

// final scan: warp 0 does a parallel shfl-scan of the 25 tile sums (was a serial
// dependent-LDG loop costing ~9us); then block-local Hillis-Steele as before.
__global__ void k_scan_final() {
    __shared__ int ssum[SCAN_BLOCK];
    __shared__ int s_tileOff;
    int t = threadIdx.x, b = blockIdx.x;
    int base = b * SCAN_TILE;

    if (t < 32) {
        int v = (t < NTILES) ? d_tileSum[t] : 0;
        int incl = v;
#pragma unroll
        for (int o = 1; o < 32; o <<= 1) {
            int u = __shfl_up_sync(0xffffffff, incl, o);
            if (t >= o) incl += u;
        }
        if (t == b) s_tileOff = incl - v;   // exclusive prefix for this block
    }

    int tc[SCAN_ITEMS], v[SCAN_ITEMS];
    int s = 0;
#pragma unroll
    for (int i = 0; i < SCAN_ITEMS; i++) {
        int idx = base + t * SCAN_ITEMS + i;
        tc[i] = (idx < NN) ? d_rowcnt[idx] : 0;
        v[i] = (idx < NN) ? padded(tc[i]) : 0;
        s += v[i];
    }
    ssum[t] = s;
    __syncthreads();
    for (int o = 1; o < SCAN_BLOCK; o <<= 1) {
        int val = ssum[t];
        int add = (t >= o) ? ssum[t - o] : 0;
        __syncthreads();
        ssum[t] = val + add;
        __syncthreads();
    }
    int run = ((t > 0) ? ssum[t - 1] : 0) + s_tileOff;
#pragma unroll
    for (int i = 0; i < SCAN_ITEMS; i++) {
        int idx = base + t * SCAN_ITEMS + i;
        if (idx < NN) {
            d_rowptr[idx] = run;
            d_cursor[idx] = run;
            if (tc[i] & 1)
                d_edges[run + tc[i]] = make_int2(0, 0);   // pad slot w=0
            run += v[i];
        }
    }
}

__global__ void k_fill_buildG(const int* __restrict__ row, const int* __restrict__ col,
                              const float* __restrict__ Z, const float* __restrict__ Y) {
    int idx = blockIdx.x * blockDim.x + threadIdx.x;
    if (idx < EE) {
        int r = row[idx], c = col[idx];
        float w = LAMF * d_dinv[r] * d_dinv[c];
        int pos = atomicAdd(&d_cursor[r], 1);
        d_edges[pos] = make_int2(c, __float_as_int(w));
    }
    if (idx < NN * CC) {
        int n = idx / CC, c = idx % CC;
        int wi = d_winner[n];
        float g = (wi >= 0) ? Y[wi * CC + c] : Z[idx];
        float g01 = OMLAMF * g;
        d_G01f[idx] = g01;
        d_G01h[idx] = __float2half_rn(g01);
        d_xB[(size_t)n * XSTRIDE + c] = __float2half_rn(g);   // x0, padded stride
    }
}

// ---------------- SpMM: warp-per-row, half-warp per edge, no selects ----------
// Lane's half h reads its own int2 edge at ep2[2j] (ep2 pre-offset by h) —
// one warp LDG covers both halves' edges (same 16B line). One-ahead prefetch
// is unconditional (slack slots). 12 of 16 lanes gather uint2 (8B) of x-row.
template <bool FINAL>
__global__ __launch_bounds__(256, 8) void k_spmm(const __half* __restrict__ x,
                                                 void* __restrict__ outp) {
    int gw = (blockIdx.x * blockDim.x + threadIdx.x) >> 5;
    if (gw >= NN) return;
    const int lane = threadIdx.x & 31;
    const int half = lane >> 4;
    const int sub = lane & 15;
    const bool active = sub < 12;
    const unsigned bofs = sub * 8;   // byte offset of this lane's uint2 in a row

    const int np = (d_rowcnt[gw] + 1) >> 1;                 // pair count (>=1)
    const int2* ep2 = d_edges + d_rowptr[gw] + half;        // this half's stream
    const char* xb = (const char*)x;

    float4 acc = make_float4(0.f, 0.f, 0.f, 0.f);
    int2 e = __ldg(ep2);
    for (int j = 1; j <= np; j++) {
        int2 en = __ldg(ep2 + 2 * j);   // unconditional: slack slots cover overread
        unsigned c = (unsigned)e.x;
        float w = __int_as_float(e.y);
        if (active) {
            uint2 raw = __ldg((const uint2*)(xb + (c << 7) + bofs));
            __half2 h0, h1;
            *reinterpret_cast<unsigned*>(&h0) = raw.x;
            *reinterpret_cast<unsigned*>(&h1) = raw.y;
            float2 f0 = __half22float2(h0);
            float2 f1 = __half22float2(h1);
            acc.x = fmaf(w, f0.x, acc.x);
            acc.y = fmaf(w, f0.y, acc.y);
            acc.z = fmaf(w, f1.x, acc.z);
            acc.w = fmaf(w, f1.y, acc.w);
        }
        e = en;
    }

    acc.x += __shfl_xor_sync(0xffffffff, acc.x, 16);
    acc.y += __shfl_xor_sync(0xffffffff, acc.y, 16);
    acc.z += __shfl_xor_sync(0xffffffff, acc.z, 16);
    acc.w += __shfl_xor_sync(0xffffffff, acc.w, 16);

    if (half == 0 && active) {
        unsigned go = (unsigned)gw * CC + sub * 4;
        if (FINAL) {
            const float4 g = *(const float4*)(d_G01f + go);
            float4 o;
            o.x = acc.x + g.x;
            o.y = acc.y + g.y;
            o.z = acc.z + g.z;
            o.w = acc.w + g.w;
            *(float4*)((float*)outp + go) = o;
        } else {
            uint2 graw = *(const uint2*)(d_G01h + go);
            __half2 g0, g1;
            *reinterpret_cast<unsigned*>(&g0) = graw.x;
            *reinterpret_cast<unsigned*>(&g1) = graw.y;
            float2 gf0 = __half22float2(g0);
            float2 gf1 = __half22float2(g1);
            __half2 o0 = __floats2half2_rn(acc.x + gf0.x, acc.y + gf0.y);
            __half2 o1 = __floats2half2_rn(acc.z + gf1.x, acc.w + gf1.y);
            uint2 st;
            st.x = *reinterpret_cast<unsigned*>(&o0);
            st.y = *reinterpret_cast<unsigned*>(&o1);
            *(uint2*)((char*)outp + ((unsigned)gw << 7) + bofs) = st;
        }
    }
}

// ---------------- launch ----------------
extern "C" void kernel_launch(void* const* d_in, const int* in_sizes, int n_in,
                              void* d_out, int out_size) {
    const float* Z = (const float*)d_in[0];
    const float* Y = (const float*)d_in[1];
    const int* mask = (const int*)d_in[2];
    const int* ei = (const int*)d_in[3];   // [2, E]: row then col
    const int* row = ei;
    const int* col = ei + EE;

    __half *xA, *xB;
    cudaGetSymbolAddress((void**)&xA, d_xA);
    cudaGetSymbolAddress((void**)&xB, d_xB);

    const int tb = 256;
    k_init<<<(NN + tb - 1) / tb, tb>>>();
    k_count<<<(EE + tb - 1) / tb, tb>>>(row, col, mask);
    k_scan_reduce<<<NTILES, SCAN_BLOCK>>>();
    k_scan_final<<<NTILES, SCAN_BLOCK>>>();
    k_fill_buildG<<<(NN * CC + tb - 1) / tb, tb>>>(row, col, Z, Y);

    const int spmm_blocks = (NN * 32 + tb - 1) / tb;
    const __half* cur = xB;                  // x0
    for (int it = 0; it < LL - 1; ++it) {
        __half* nxt = (it & 1) ? xB : xA;
        k_spmm<false><<<spmm_blocks, tb>>>(cur, nxt);
        cur = nxt;
    }
    k_spmm<true><<<spmm_blocks, tb>>>(cur, d_out);
}

// round 10
// speedup vs baseline: 1.4079x; 1.0150x over previous
#include <cuda_runtime.h>
#include <cuda_fp16.h>

// Problem constants (fixed by the dataset)
#define NN 100000
#define CC 48
#define EE 1600000
#define MM 20000
#define LL 10
#define LAMF 0.9f
#define OMLAMF 0.1f

#define XSTRIDE 64   // halves per x-row (128B padded) -> gathers hit one cache line

#define SCAN_BLOCK 1024
#define SCAN_ITEMS 4
#define SCAN_TILE  (SCAN_BLOCK * SCAN_ITEMS)            // 4096
#define NTILES     ((NN + SCAN_TILE - 1) / SCAN_TILE)   // 25

// padded edge capacity: rows padded to even count; +6 slack for depth-2 overread
#define PADE  (EE + NN + 6)

// ---------------- device scratch (no allocations allowed) ----------------
__device__ int    d_deg[NN];
__device__ float  d_dinv[NN];
__device__ int    d_rowcnt[NN];       // true out-count per row
__device__ int    d_rowptr[NN];       // CSR offsets in PADDED (even) int2 space
__device__ int    d_cursor[NN];
__device__ int    d_winner[NN];       // last mask index targeting node (-1)
__device__ int2   d_edges[PADE];      // {col, w}; w prescaled by LAM; pads w=0
__device__ float  d_G01f[NN * CC];    // 0.1*G fp32 (final iter)
__device__ __half d_G01h[NN * CC];    // 0.1*G fp16 (intermediate iters)
__device__ __half d_xA[NN * XSTRIDE]; // fp16 ping (128B row stride)
__device__ __half d_xB[NN * XSTRIDE]; // fp16 pong (holds x0)
__device__ int    d_tileSum[NTILES];

__device__ __forceinline__ int padded(int c) { return (c + 1) & ~1; }

// ---------------- preprocessing (5 kernels) ----------------
__global__ void k_init() {
    int i = blockIdx.x * blockDim.x + threadIdx.x;
    if (i < NN) {
        d_deg[i] = 0;
        d_rowcnt[i] = 0;
        d_winner[i] = -1;
    }
    if (i < 6) d_edges[EE + NN + i] = make_int2(0, 0);   // prefetch slack
}

__global__ void k_count(const int* __restrict__ row, const int* __restrict__ col,
                        const int* __restrict__ mask) {
    int e = blockIdx.x * blockDim.x + threadIdx.x;
    if (e < EE) {
        atomicAdd(&d_rowcnt[row[e]], 1);
        atomicAdd(&d_deg[col[e]], 1);
    }
    if (e < MM) atomicMax(&d_winner[mask[e]], e);
}

__global__ void k_scan_reduce() {
    __shared__ int sdata[SCAN_BLOCK];
    int t = threadIdx.x, b = blockIdx.x;
    int base = b * SCAN_TILE;
    int s = 0;
#pragma unroll
    for (int i = 0; i < SCAN_ITEMS; i++) {
        int idx = base + t + i * SCAN_BLOCK;
        if (idx < NN) {
            s += padded(d_rowcnt[idx]);
            d_dinv[idx] = rsqrtf((float)d_deg[idx]);   // deg >= 1 guaranteed
        }
    }
    sdata[t] = s;
    __syncthreads();
    for (int o = SCAN_BLOCK / 2; o > 0; o >>= 1) {
        if (t < o) sdata[t] += sdata[t + o];
        __syncthreads();
    }
    if (t == 0) d_tileSum[b] = sdata[0];
}

// final scan: warp 0 shfl-scans the 25 tile sums; block Hillis-Steele; writes
// rowptr/cursor and the w=0 pad slot for odd-count rows.
__global__ void k_scan_final() {
    __shared__ int ssum[SCAN_BLOCK];
    __shared__ int s_tileOff;
    int t = threadIdx.x, b = blockIdx.x;
    int base = b * SCAN_TILE;

    if (t < 32) {
        int v = (t < NTILES) ? d_tileSum[t] : 0;
        int incl = v;
#pragma unroll
        for (int o = 1; o < 32; o <<= 1) {
            int u = __shfl_up_sync(0xffffffff, incl, o);
            if (t >= o) incl += u;
        }
        if (t == b) s_tileOff = incl - v;   // exclusive prefix for this block
    }

    int tc[SCAN_ITEMS], v[SCAN_ITEMS];
    int s = 0;
#pragma unroll
    for (int i = 0; i < SCAN_ITEMS; i++) {
        int idx = base + t * SCAN_ITEMS + i;
        tc[i] = (idx < NN) ? d_rowcnt[idx] : 0;
        v[i] = (idx < NN) ? padded(tc[i]) : 0;
        s += v[i];
    }
    ssum[t] = s;
    __syncthreads();
    for (int o = 1; o < SCAN_BLOCK; o <<= 1) {
        int val = ssum[t];
        int add = (t >= o) ? ssum[t - o] : 0;
        __syncthreads();
        ssum[t] = val + add;
        __syncthreads();
    }
    int run = ((t > 0) ? ssum[t - 1] : 0) + s_tileOff;
#pragma unroll
    for (int i = 0; i < SCAN_ITEMS; i++) {
        int idx = base + t * SCAN_ITEMS + i;
        if (idx < NN) {
            d_rowptr[idx] = run;
            d_cursor[idx] = run;
            if (tc[i] & 1)
                d_edges[run + tc[i]] = make_int2(0, 0);   // pad slot w=0
            run += v[i];
        }
    }
}

__global__ void k_fill_buildG(const int* __restrict__ row, const int* __restrict__ col,
                              const float* __restrict__ Z, const float* __restrict__ Y) {
    int idx = blockIdx.x * blockDim.x + threadIdx.x;
    if (idx < EE) {
        int r = row[idx], c = col[idx];
        float w = LAMF * d_dinv[r] * d_dinv[c];
        int pos = atomicAdd(&d_cursor[r], 1);
        d_edges[pos] = make_int2(c, __float_as_int(w));
    }
    if (idx < NN * CC) {
        int n = idx / CC, c = idx % CC;
        int wi = d_winner[n];
        float g = (wi >= 0) ? Y[wi * CC + c] : Z[idx];
        float g01 = OMLAMF * g;
        d_G01f[idx] = g01;
        d_G01h[idx] = __float2half_rn(g01);
        d_xB[(size_t)n * XSTRIDE + c] = __float2half_rn(g);   // x0, padded stride
    }
}

// ---------------- SpMM: warp-per-row, depth-2 software pipeline ---------------
// Half h's edge stream: ep2[2j] (pre-offset by h). Steady state of trip j:
//   load edge j+2 ; issue gather for edge j+1 ; FMA with gather of edge j.
// Gathers thus have one full trip of slack before consumption. All loads are
// unconditional (slack slots at the end of d_edges cover the overread; pads w=0).
template <bool FINAL>
__global__ __launch_bounds__(256, 8) void k_spmm(const __half* __restrict__ x,
                                                 void* __restrict__ outp) {
    int gw = (blockIdx.x * blockDim.x + threadIdx.x) >> 5;
    if (gw >= NN) return;
    const int lane = threadIdx.x & 31;
    const int half = lane >> 4;
    const int sub = lane & 15;
    const bool active = sub < 12;
    const unsigned bofs = sub * 8;   // byte offset of this lane's uint2 in a row

    const int np = (d_rowcnt[gw] + 1) >> 1;                 // pair count (>=1)
    const int2* ep2 = d_edges + d_rowptr[gw] + half;        // this half's stream
    const char* xb = (const char*)x;

    float4 acc = make_float4(0.f, 0.f, 0.f, 0.f);

    // prologue: edge0, edge1, gather0
    int2 e0 = __ldg(ep2);
    int2 e1 = __ldg(ep2 + 2);
    uint2 r0 = make_uint2(0u, 0u);
    if (active) r0 = __ldg((const uint2*)(xb + (((unsigned)e0.x) << 7) + bofs));
    float w0 = __int_as_float(e0.y);

    for (int j = 0; j < np; j++) {
        // load edge j+2 (unconditional; slack-covered)
        int2 e2 = __ldg(ep2 + 2 * (j + 2));
        // gather for edge j+1 (e1 loaded two trips ago -> address ready)
        uint2 r1 = make_uint2(0u, 0u);
        if (active) r1 = __ldg((const uint2*)(xb + (((unsigned)e1.x) << 7) + bofs));
        float w1 = __int_as_float(e1.y);
        // consume gather j (issued one trip ago)
        if (active) {
            __half2 h0, h1;
            *reinterpret_cast<unsigned*>(&h0) = r0.x;
            *reinterpret_cast<unsigned*>(&h1) = r0.y;
            float2 f0 = __half22float2(h0);
            float2 f1 = __half22float2(h1);
            acc.x = fmaf(w0, f0.x, acc.x);
            acc.y = fmaf(w0, f0.y, acc.y);
            acc.z = fmaf(w0, f1.x, acc.z);
            acc.w = fmaf(w0, f1.y, acc.w);
        }
        e1 = e2;
        r0 = r1;
        w0 = w1;
    }

    acc.x += __shfl_xor_sync(0xffffffff, acc.x, 16);
    acc.y += __shfl_xor_sync(0xffffffff, acc.y, 16);
    acc.z += __shfl_xor_sync(0xffffffff, acc.z, 16);
    acc.w += __shfl_xor_sync(0xffffffff, acc.w, 16);

    if (half == 0 && active) {
        unsigned go = (unsigned)gw * CC + sub * 4;
        if (FINAL) {
            const float4 g = *(const float4*)(d_G01f + go);
            float4 o;
            o.x = acc.x + g.x;
            o.y = acc.y + g.y;
            o.z = acc.z + g.z;
            o.w = acc.w + g.w;
            *(float4*)((float*)outp + go) = o;
        } else {
            uint2 graw = *(const uint2*)(d_G01h + go);
            __half2 g0, g1;
            *reinterpret_cast<unsigned*>(&g0) = graw.x;
            *reinterpret_cast<unsigned*>(&g1) = graw.y;
            float2 gf0 = __half22float2(g0);
            float2 gf1 = __half22float2(g1);
            __half2 o0 = __floats2half2_rn(acc.x + gf0.x, acc.y + gf0.y);
            __half2 o1 = __floats2half2_rn(acc.z + gf1.x, acc.w + gf1.y);
            uint2 st;
            st.x = *reinterpret_cast<unsigned*>(&o0);
            st.y = *reinterpret_cast<unsigned*>(&o1);
            *(uint2*)((char*)outp + ((unsigned)gw << 7) + bofs) = st;
        }
    }
}

// ---------------- launch ----------------
extern "C" void kernel_launch(void* const* d_in, const int* in_sizes, int n_in,
                              void* d_out, int out_size) {
    const float* Z = (const float*)d_in[0];
    const float* Y = (const float*)d_in[1];
    const int* mask = (const int*)d_in[2];
    const int* ei = (const int*)d_in[3];   // [2, E]: row then col
    const int* row = ei;
    const int* col = ei + EE;

    __half *xA, *xB;
    cudaGetSymbolAddress((void**)&xA, d_xA);
    cudaGetSymbolAddress((void**)&xB, d_xB);

    const int tb = 256;
    k_init<<<(NN + tb - 1) / tb, tb>>>();
    k_count<<<(EE + tb - 1) / tb, tb>>>(row, col, mask);
    k_scan_reduce<<<NTILES, SCAN_BLOCK>>>();
    k_scan_final<<<NTILES, SCAN_BLOCK>>>();
    k_fill_buildG<<<(NN * CC + tb - 1) / tb, tb>>>(row, col, Z, Y);

    const int spmm_blocks = (NN * 32 + tb - 1) / tb;
    const __half* cur = xB;                  // x0
    for (int it = 0; it < LL - 1; ++it) {
        __half* nxt = (it & 1) ? xB : xA;
        k_spmm<false><<<spmm_blocks, tb>>>(cur, nxt);
        cur = nxt;
    }
    k_spmm<true><<<spmm_blocks, tb>>>(cur, d_out);
}

// round 11
// speedup vs baseline: 1.5740x; 1.1179x over previous
#include <cuda_runtime.h>
#include <cuda_fp16.h>

// Problem constants (fixed by the dataset)
#define NN 100000
#define CC 48
#define EE 1600000
#define MM 20000
#define LL 10
#define LAMF 0.9f
#define OMLAMF 0.1f

#define XSTRIDE 64   // halves per x-row (128B padded) -> gathers hit one cache line

#define SCAN_BLOCK 1024
#define SCAN_ITEMS 4
#define SCAN_TILE  (SCAN_BLOCK * SCAN_ITEMS)            // 4096
#define NTILES     ((NN + SCAN_TILE - 1) / SCAN_TILE)   // 25

// padded edge capacity: rows padded to even count; +6 slack for depth-2 overread
#define PADE  (EE + NN + 6)

// ---------------- device scratch (no allocations allowed) ----------------
__device__ int    d_deg[NN];
__device__ float  d_dinv[NN];
__device__ int    d_rowcnt[NN];       // true out-count per row
__device__ int2   d_rowmeta[NN];      // {rowptr (padded int2 space), rowcnt}
__device__ int    d_cursor[NN];
__device__ int    d_winner[NN];       // last mask index targeting node (-1)
__device__ int2   d_edges[PADE];      // {col, w}; w prescaled by LAM; pads w=0
__device__ __half d_G01h[NN * CC];    // 0.1*G  (fp16)
__device__ __half d_xA[NN * XSTRIDE]; // fp16 ping (128B row stride)
__device__ __half d_xB[NN * XSTRIDE]; // fp16 pong (holds x0)
__device__ int    d_tileSum[NTILES];

__device__ __forceinline__ int padded(int c) { return (c + 1) & ~1; }

// ---------------- preprocessing (5 kernels) ----------------
__global__ void k_init() {
    int i = blockIdx.x * blockDim.x + threadIdx.x;
    if (i < NN) {
        d_deg[i] = 0;
        d_rowcnt[i] = 0;
        d_winner[i] = -1;
    }
    if (i < 6) d_edges[EE + NN + i] = make_int2(0, 0);   // prefetch slack
}

// 2 edges per thread (int2 loads); winner selection fused
__global__ void k_count(const int2* __restrict__ row2, const int2* __restrict__ col2,
                        const int* __restrict__ mask) {
    int e = blockIdx.x * blockDim.x + threadIdx.x;
    if (e < EE / 2) {
        int2 r = __ldg(row2 + e);
        int2 c = __ldg(col2 + e);
        atomicAdd(&d_rowcnt[r.x], 1);
        atomicAdd(&d_rowcnt[r.y], 1);
        atomicAdd(&d_deg[c.x], 1);
        atomicAdd(&d_deg[c.y], 1);
    }
    if (e < MM) atomicMax(&d_winner[mask[e]], e);
}

__global__ void k_scan_reduce() {
    __shared__ int sdata[SCAN_BLOCK];
    int t = threadIdx.x, b = blockIdx.x;
    int base = b * SCAN_TILE;
    int s = 0;
#pragma unroll
    for (int i = 0; i < SCAN_ITEMS; i++) {
        int idx = base + t + i * SCAN_BLOCK;
        if (idx < NN) {
            s += padded(d_rowcnt[idx]);
            d_dinv[idx] = rsqrtf((float)d_deg[idx]);   // deg >= 1 guaranteed
        }
    }
    sdata[t] = s;
    __syncthreads();
    for (int o = SCAN_BLOCK / 2; o > 0; o >>= 1) {
        if (t < o) sdata[t] += sdata[t + o];
        __syncthreads();
    }
    if (t == 0) d_tileSum[b] = sdata[0];
}

// final scan: warp 0 shfl-scans the 25 tile sums; block Hillis-Steele; writes
// rowmeta/cursor and the w=0 pad slot for odd-count rows.
__global__ void k_scan_final() {
    __shared__ int ssum[SCAN_BLOCK];
    __shared__ int s_tileOff;
    int t = threadIdx.x, b = blockIdx.x;
    int base = b * SCAN_TILE;

    if (t < 32) {
        int v = (t < NTILES) ? d_tileSum[t] : 0;
        int incl = v;
#pragma unroll
        for (int o = 1; o < 32; o <<= 1) {
            int u = __shfl_up_sync(0xffffffff, incl, o);
            if (t >= o) incl += u;
        }
        if (t == b) s_tileOff = incl - v;   // exclusive prefix for this block
    }

    int tc[SCAN_ITEMS], v[SCAN_ITEMS];
    int s = 0;
#pragma unroll
    for (int i = 0; i < SCAN_ITEMS; i++) {
        int idx = base + t * SCAN_ITEMS + i;
        tc[i] = (idx < NN) ? d_rowcnt[idx] : 0;
        v[i] = (idx < NN) ? padded(tc[i]) : 0;
        s += v[i];
    }
    ssum[t] = s;
    __syncthreads();
    for (int o = 1; o < SCAN_BLOCK; o <<= 1) {
        int val = ssum[t];
        int add = (t >= o) ? ssum[t - o] : 0;
        __syncthreads();
        ssum[t] = val + add;
        __syncthreads();
    }
    int run = ((t > 0) ? ssum[t - 1] : 0) + s_tileOff;
#pragma unroll
    for (int i = 0; i < SCAN_ITEMS; i++) {
        int idx = base + t * SCAN_ITEMS + i;
        if (idx < NN) {
            d_rowmeta[idx] = make_int2(run, tc[i]);
            d_cursor[idx] = run;
            if (tc[i] & 1)
                d_edges[run + tc[i]] = make_int2(0, 0);   // pad slot w=0
            run += v[i];
        }
    }
}

__global__ void k_fill_buildG(const int* __restrict__ row, const int* __restrict__ col,
                              const float* __restrict__ Z, const float* __restrict__ Y) {
    int idx = blockIdx.x * blockDim.x + threadIdx.x;
    if (idx < EE) {
        int r = row[idx], c = col[idx];
        float w = LAMF * d_dinv[r] * d_dinv[c];
        int pos = atomicAdd(&d_cursor[r], 1);
        d_edges[pos] = make_int2(c, __float_as_int(w));
    }
    if (idx < NN * CC) {
        int n = idx / CC, c = idx % CC;
        int wi = d_winner[n];
        float g = (wi >= 0) ? Y[wi * CC + c] : Z[idx];
        d_G01h[idx] = __float2half_rn(OMLAMF * g);
        d_xB[(size_t)n * XSTRIDE + c] = __float2half_rn(g);   // x0, padded stride
    }
}

// ---------------- SpMM: warp-per-row, depth-2 pipeline, G-preloaded acc -------
// Half h's edge stream: ep2[2j] (pre-offset by h). Steady state of trip j:
//   load edge j+2 ; issue gather for edge j+1 ; FMA with gather of edge j.
// acc of half 0 is pre-initialized with 0.1*G (loaded in the prologue where its
// latency is fully hidden), so the epilogue is convert+store only.
template <bool FINAL>
__global__ __launch_bounds__(256, 8) void k_spmm(const __half* __restrict__ x,
                                                 void* __restrict__ outp) {
    int gw = (blockIdx.x * blockDim.x + threadIdx.x) >> 5;
    if (gw >= NN) return;
    const int lane = threadIdx.x & 31;
    const int half = lane >> 4;
    const int sub = lane & 15;
    const bool active = sub < 12;
    const unsigned bofs = sub * 8;   // byte offset of this lane's uint2 in a row

    const int2 meta = __ldg(&d_rowmeta[gw]);                // {ptr, cnt}
    const int np = (meta.y + 1) >> 1;                       // pair count
    const int2* ep2 = d_edges + meta.x + half;              // this half's stream
    const char* xb = (const char*)x;

    // prologue: edges 0,1 + gather 0 + G preload (half 0 only)
    int2 e0 = __ldg(ep2);
    int2 e1 = __ldg(ep2 + 2);
    uint2 r0 = make_uint2(0u, 0u);
    if (active) r0 = __ldg((const uint2*)(xb + (((unsigned)e0.x) << 7) + bofs));
    float w0 = __int_as_float(e0.y);

    float4 acc = make_float4(0.f, 0.f, 0.f, 0.f);
    const unsigned go = (unsigned)gw * CC + sub * 4;
    if (half == 0 && active) {
        uint2 graw = __ldg((const uint2*)(d_G01h + go));
        __half2 g0, g1;
        *reinterpret_cast<unsigned*>(&g0) = graw.x;
        *reinterpret_cast<unsigned*>(&g1) = graw.y;
        float2 gf0 = __half22float2(g0);
        float2 gf1 = __half22float2(g1);
        acc = make_float4(gf0.x, gf0.y, gf1.x, gf1.y);
    }

    for (int j = 0; j < np; j++) {
        int2 e2 = __ldg(ep2 + 2 * (j + 2));   // unconditional; slack-covered
        uint2 r1 = make_uint2(0u, 0u);
        if (active) r1 = __ldg((const uint2*)(xb + (((unsigned)e1.x) << 7) + bofs));
        float w1 = __int_as_float(e1.y);
        if (active) {
            __half2 h0, h1;
            *reinterpret_cast<unsigned*>(&h0) = r0.x;
            *reinterpret_cast<unsigned*>(&h1) = r0.y;
            float2 f0 = __half22float2(h0);
            float2 f1 = __half22float2(h1);
            acc.x = fmaf(w0, f0.x, acc.x);
            acc.y = fmaf(w0, f0.y, acc.y);
            acc.z = fmaf(w0, f1.x, acc.z);
            acc.w = fmaf(w0, f1.y, acc.w);
        }
        e1 = e2;
        r0 = r1;
        w0 = w1;
    }

    acc.x += __shfl_xor_sync(0xffffffff, acc.x, 16);
    acc.y += __shfl_xor_sync(0xffffffff, acc.y, 16);
    acc.z += __shfl_xor_sync(0xffffffff, acc.z, 16);
    acc.w += __shfl_xor_sync(0xffffffff, acc.w, 16);

    if (half == 0 && active) {
        if (FINAL) {
            *(float4*)((float*)outp + go) = acc;
        } else {
            __half2 o0 = __floats2half2_rn(acc.x, acc.y);
            __half2 o1 = __floats2half2_rn(acc.z, acc.w);
            uint2 st;
            st.x = *reinterpret_cast<unsigned*>(&o0);
            st.y = *reinterpret_cast<unsigned*>(&o1);
            *(uint2*)((char*)outp + ((unsigned)gw << 7) + bofs) = st;
        }
    }
}

// ---------------- launch ----------------
extern "C" void kernel_launch(void* const* d_in, const int* in_sizes, int n_in,
                              void* d_out, int out_size) {
    const float* Z = (const float*)d_in[0];
    const float* Y = (const float*)d_in[1];
    const int* mask = (const int*)d_in[2];
    const int* ei = (const int*)d_in[3];   // [2, E]: row then col
    const int* row = ei;
    const int* col = ei + EE;

    __half *xA, *xB;
    cudaGetSymbolAddress((void**)&xA, d_xA);
    cudaGetSymbolAddress((void**)&xB, d_xB);

    const int tb = 256;
    k_init<<<(NN + tb - 1) / tb, tb>>>();
    k_count<<<(EE / 2 + tb - 1) / tb, tb>>>((const int2*)row, (const int2*)col, mask);
    k_scan_reduce<<<NTILES, SCAN_BLOCK>>>();
    k_scan_final<<<NTILES, SCAN_BLOCK>>>();
    k_fill_buildG<<<(NN * CC + tb - 1) / tb, tb>>>(row, col, Z, Y);

    const int spmm_blocks = (NN * 32 + tb - 1) / tb;
    const __half* cur = xB;                  // x0
    for (int it = 0; it < LL - 1; ++it) {
        __half* nxt = (it & 1) ? xB : xA;
        k_spmm<false><<<spmm_blocks, tb>>>(cur, nxt);
        cur = nxt;
    }
    k_spmm<true><<<spmm_blocks, tb>>>(cur, d_out);
}